// round 2
// baseline (speedup 1.0000x reference)
#include <cuda_runtime.h>

// ---------------- problem constants (fixed shapes) ----------------
#define B_  16
#define MQ  4          // CLS tokens
#define NF  12         // frames
#define LF  196        // tokens per frame
#define HH  12         // heads
#define DH  64         // head dim
#define EW  768        // embed dim
#define TT  2356       // MQ + NF*LF
#define ROWS (B_*TT)   // 37696
#define KL  200        // MQ + LF (frame attention key length)

// ---------------- scratch (no cudaMalloc allowed) ----------------
__device__ float g_q[ROWS * EW];    // (B,T,E) layout, E index = h*64+dd
__device__ float g_k[ROWS * EW];
__device__ float g_v[ROWS * EW];
__device__ float g_ctx[ROWS * EW];

// =================================================================
// SGEMM: C(ROWS x 768) = A(ROWS x 768) @ W(768 x 768), epilogue
// C = (acc + bias[n]) * scale.   Tiles: BM=64, BN=128, BK=16.
// grid = (6, 589), block = 256 threads, 8 cols x 4 rows per thread.
// Software-pipelined: next k-tile prefetched to registers during
// the FFMA phase of the current tile.
// =================================================================
__global__ __launch_bounds__(256) void sgemm_bias(
    const float* __restrict__ A, const float* __restrict__ W,
    const float* __restrict__ bias, float* __restrict__ C, float scale)
{
    __shared__ float As[16][68];    // [k][m], padded
    __shared__ float Bs[16][132];   // [k][n], padded (stride 528B, 16B-aligned)

    const int tid = threadIdx.x;
    const int m0 = blockIdx.y * 64;
    const int n0 = blockIdx.x * 128;
    const int ty = tid >> 4;        // 0..15 -> 4 rows each
    const int tx = tid & 15;        // 0..15 -> 8 cols each

    // A load: one float4 per thread per k-step
    const int ar = tid >> 2;            // 0..63
    const int ak = (tid & 3) << 2;      // 0,4,8,12
    // B load: two float4 per thread per k-step
    const int br = tid >> 5;            // 0..7
    const int bc = (tid & 31) << 2;     // 0..124

    const float* Ap  = A + (size_t)(m0 + ar) * EW + ak;
    const float* Wp0 = W + (size_t)br       * EW + n0 + bc;
    const float* Wp1 = W + (size_t)(br + 8) * EW + n0 + bc;

    float acc[4][8];
#pragma unroll
    for (int i = 0; i < 4; i++)
#pragma unroll
        for (int j = 0; j < 8; j++) acc[i][j] = 0.f;

    // prologue: fetch tile 0
    float4 a4 = *(const float4*)(Ap);
    float4 b0 = *(const float4*)(Wp0);
    float4 b1 = *(const float4*)(Wp1);

    for (int k0 = 0; k0 < EW; k0 += 16) {
        As[ak + 0][ar] = a4.x;
        As[ak + 1][ar] = a4.y;
        As[ak + 2][ar] = a4.z;
        As[ak + 3][ar] = a4.w;
        *(float4*)&Bs[br][bc]     = b0;
        *(float4*)&Bs[br + 8][bc] = b1;
        __syncthreads();

        // prefetch next tile into registers (overlaps with FFMAs below)
        if (k0 + 16 < EW) {
            a4 = *(const float4*)(Ap + k0 + 16);
            b0 = *(const float4*)(Wp0 + (size_t)(k0 + 16) * EW);
            b1 = *(const float4*)(Wp1 + (size_t)(k0 + 16) * EW);
        }

#pragma unroll
        for (int kk = 0; kk < 16; kk++) {
            float4 av  = *(const float4*)&As[kk][ty * 4];
            float4 bv0 = *(const float4*)&Bs[kk][tx * 8];
            float4 bv1 = *(const float4*)&Bs[kk][tx * 8 + 4];
            float a[4] = {av.x, av.y, av.z, av.w};
            float b[8] = {bv0.x, bv0.y, bv0.z, bv0.w, bv1.x, bv1.y, bv1.z, bv1.w};
#pragma unroll
            for (int i = 0; i < 4; i++)
#pragma unroll
                for (int j = 0; j < 8; j++) acc[i][j] += a[i] * b[j];
        }
        __syncthreads();
    }

    float bz[8];
#pragma unroll
    for (int j = 0; j < 8; j++) bz[j] = bias[n0 + tx * 8 + j];

#pragma unroll
    for (int i = 0; i < 4; i++) {
        float* Cr = C + (size_t)(m0 + ty * 4 + i) * EW + n0 + tx * 8;
#pragma unroll
        for (int j = 0; j < 8; j++) Cr[j] = (acc[i][j] + bz[j]) * scale;
    }
}

// =================================================================
// Frame attention: one block per (b,h,n). K/V (200x64) resident in
// SMEM (stride-65, conflict-free). Each warp processes 4 q-rows per
// pass; scores/probs per-warp in SMEM; PV with 2 dims per lane.
// Writes directly into ctx (B,T,E) at t = MQ + n*LF + l.
// =================================================================
#define FRAME_SMEM_FLOATS (KL*65*2 + 32*DH + 32*KL)
#define FRAME_SMEM_BYTES  (FRAME_SMEM_FLOATS * 4)

__global__ __launch_bounds__(256) void frame_attn(
    const float* __restrict__ q, const float* __restrict__ k,
    const float* __restrict__ v, float* __restrict__ ctx)
{
    extern __shared__ float sm[];
    float* Ks = sm;                  // [200][65]
    float* Vs = Ks + KL * 65;        // [200][65]
    float* qs = Vs + KL * 65;        // [8 warps][4 rows][64]
    float* ps = qs + 32 * DH;        // [8 warps][4 rows][200]

    const int n  = blockIdx.x % NF;
    const int bh = blockIdx.x / NF;
    const int h  = bh % HH;
    const int b  = bh / HH;
    const int tid = threadIdx.x;
    const size_t base = (size_t)b * TT * EW + (size_t)h * DH;
    const int tf0 = MQ + n * LF;

    // load K,V tiles (CLS keys 0..3 + frame keys)
    for (int i = tid; i < KL * (DH / 2); i += 256) {
        int kk = i >> 5;               // key index (32 float2 per row)
        int d2 = (i & 31) << 1;
        int t  = (kk < MQ) ? kk : (tf0 + kk - MQ);
        const float2 kv2 = *(const float2*)(k + base + (size_t)t * EW + d2);
        const float2 vv2 = *(const float2*)(v + base + (size_t)t * EW + d2);
        Ks[kk * 65 + d2]     = kv2.x;
        Ks[kk * 65 + d2 + 1] = kv2.y;
        Vs[kk * 65 + d2]     = vv2.x;
        Vs[kk * 65 + d2 + 1] = vv2.y;
    }
    __syncthreads();

    const int w = tid >> 5;
    const int lane = tid & 31;
    float* qw = qs + w * 4 * DH;
    float* pw = ps + w * 4 * KL;

    for (int l0 = w * 4; l0 < LF; l0 += 32) {
        // load 4 q rows into per-warp smem
        for (int i = lane; i < 4 * DH; i += 32) {
            int r = i >> 6, d = i & 63;
            qw[r * DH + d] = q[base + (size_t)(tf0 + l0 + r) * EW + d];
        }
        __syncwarp();

        // scores: lane handles keys lane, lane+32, ...
        float mx0 = -1e30f, mx1 = -1e30f, mx2 = -1e30f, mx3 = -1e30f;
        for (int kk = lane; kk < KL; kk += 32) {
            const float* kr = Ks + kk * 65;
            float a0 = 0.f, a1 = 0.f, a2 = 0.f, a3 = 0.f;
#pragma unroll
            for (int d = 0; d < DH; d++) {
                float kv = kr[d];
                a0 += qw[d] * kv;
                a1 += qw[DH + d] * kv;
                a2 += qw[2 * DH + d] * kv;
                a3 += qw[3 * DH + d] * kv;
            }
            pw[0 * KL + kk] = a0;  mx0 = fmaxf(mx0, a0);
            pw[1 * KL + kk] = a1;  mx1 = fmaxf(mx1, a1);
            pw[2 * KL + kk] = a2;  mx2 = fmaxf(mx2, a2);
            pw[3 * KL + kk] = a3;  mx3 = fmaxf(mx3, a3);
        }
#pragma unroll
        for (int s = 16; s; s >>= 1) {
            mx0 = fmaxf(mx0, __shfl_xor_sync(0xffffffffu, mx0, s));
            mx1 = fmaxf(mx1, __shfl_xor_sync(0xffffffffu, mx1, s));
            mx2 = fmaxf(mx2, __shfl_xor_sync(0xffffffffu, mx2, s));
            mx3 = fmaxf(mx3, __shfl_xor_sync(0xffffffffu, mx3, s));
        }

        // exp + sum
        float s0 = 0.f, s1 = 0.f, s2 = 0.f, s3 = 0.f;
        for (int kk = lane; kk < KL; kk += 32) {
            float e0 = __expf(pw[0 * KL + kk] - mx0); pw[0 * KL + kk] = e0; s0 += e0;
            float e1 = __expf(pw[1 * KL + kk] - mx1); pw[1 * KL + kk] = e1; s1 += e1;
            float e2 = __expf(pw[2 * KL + kk] - mx2); pw[2 * KL + kk] = e2; s2 += e2;
            float e3 = __expf(pw[3 * KL + kk] - mx3); pw[3 * KL + kk] = e3; s3 += e3;
        }
#pragma unroll
        for (int s = 16; s; s >>= 1) {
            s0 += __shfl_xor_sync(0xffffffffu, s0, s);
            s1 += __shfl_xor_sync(0xffffffffu, s1, s);
            s2 += __shfl_xor_sync(0xffffffffu, s2, s);
            s3 += __shfl_xor_sync(0xffffffffu, s3, s);
        }
        float i0 = 1.f / s0, i1 = 1.f / s1, i2 = 1.f / s2, i3 = 1.f / s3;
        __syncwarp();

        // PV: lane owns dims 2*lane, 2*lane+1 for all 4 rows
        const int d0 = lane << 1;
        float o00 = 0.f, o01 = 0.f, o10 = 0.f, o11 = 0.f;
        float o20 = 0.f, o21 = 0.f, o30 = 0.f, o31 = 0.f;
        for (int kk = 0; kk < KL; kk++) {
            float v0 = Vs[kk * 65 + d0];
            float v1 = Vs[kk * 65 + d0 + 1];
            float p0 = pw[0 * KL + kk];
            float p1 = pw[1 * KL + kk];
            float p2 = pw[2 * KL + kk];
            float p3 = pw[3 * KL + kk];
            o00 += p0 * v0; o01 += p0 * v1;
            o10 += p1 * v0; o11 += p1 * v1;
            o20 += p2 * v0; o21 += p2 * v1;
            o30 += p3 * v0; o31 += p3 * v1;
        }
        {
            size_t o = base + (size_t)(tf0 + l0) * EW + d0;
            ctx[o]              = o00 * i0;  ctx[o + 1]              = o01 * i0;
            ctx[o + EW]         = o10 * i1;  ctx[o + EW + 1]         = o11 * i1;
            ctx[o + 2 * EW]     = o20 * i2;  ctx[o + 2 * EW + 1]     = o21 * i2;
            ctx[o + 3 * EW]     = o30 * i3;  ctx[o + 3 * EW + 1]     = o31 * i3;
        }
        __syncwarp();
    }
}

// =================================================================
// CLS attention: one block per (b,h). 4 q rows attend to all 2356
// keys. Scores in static SMEM (36.8 KB), two-pass softmax, then PV
// with thread = (m,d).
// =================================================================
__global__ __launch_bounds__(256) void cls_attn(
    const float* __restrict__ q, const float* __restrict__ k,
    const float* __restrict__ v, float* __restrict__ ctx)
{
    __shared__ float S[4 * TT];
    __shared__ float qs[4 * DH];
    __shared__ float red[256];
    __shared__ float invs[4];

    const int bh = blockIdx.x;
    const int h  = bh % HH;
    const int b  = bh / HH;
    const int tid = threadIdx.x;
    const size_t base = (size_t)b * TT * EW + (size_t)h * DH;

    { // load the 4 scaled q rows
        int m = tid >> 6, d = tid & 63;
        qs[tid] = q[base + (size_t)m * EW + d];
    }
    __syncthreads();

    // pass 1: scores
    for (int kk = tid; kk < TT; kk += 256) {
        const float* kr = k + base + (size_t)kk * EW;
        float a0 = 0.f, a1 = 0.f, a2 = 0.f, a3 = 0.f;
#pragma unroll
        for (int d = 0; d < DH; d += 4) {
            float4 kv = *(const float4*)(kr + d);
            a0 += qs[d] * kv.x + qs[d + 1] * kv.y + qs[d + 2] * kv.z + qs[d + 3] * kv.w;
            a1 += qs[DH + d] * kv.x + qs[DH + d + 1] * kv.y + qs[DH + d + 2] * kv.z + qs[DH + d + 3] * kv.w;
            a2 += qs[2 * DH + d] * kv.x + qs[2 * DH + d + 1] * kv.y + qs[2 * DH + d + 2] * kv.z + qs[2 * DH + d + 3] * kv.w;
            a3 += qs[3 * DH + d] * kv.x + qs[3 * DH + d + 1] * kv.y + qs[3 * DH + d + 2] * kv.z + qs[3 * DH + d + 3] * kv.w;
        }
        S[0 * TT + kk] = a0;
        S[1 * TT + kk] = a1;
        S[2 * TT + kk] = a2;
        S[3 * TT + kk] = a3;
    }
    __syncthreads();

    // softmax per row (block reductions)
    for (int m = 0; m < 4; m++) {
        float lm = -1e30f;
        for (int kk = tid; kk < TT; kk += 256) lm = fmaxf(lm, S[m * TT + kk]);
        red[tid] = lm;
        __syncthreads();
        for (int s = 128; s; s >>= 1) {
            if (tid < s) red[tid] = fmaxf(red[tid], red[tid + s]);
            __syncthreads();
        }
        float mxv = red[0];
        __syncthreads();

        float ls = 0.f;
        for (int kk = tid; kk < TT; kk += 256) {
            float e = __expf(S[m * TT + kk] - mxv);
            S[m * TT + kk] = e;
            ls += e;
        }
        red[tid] = ls;
        __syncthreads();
        for (int s = 128; s; s >>= 1) {
            if (tid < s) red[tid] += red[tid + s];
            __syncthreads();
        }
        if (tid == 0) invs[m] = 1.f / red[0];
        __syncthreads();
    }

    // pass 2: PV. thread = (m, d)
    const int m = tid >> 6, d = tid & 63;
    const float* Sm = S + m * TT;
    float acc = 0.f;
#pragma unroll 4
    for (int kk = 0; kk < TT; kk++)
        acc += Sm[kk] * v[base + (size_t)kk * EW + d];
    ctx[base + (size_t)m * EW + d] = acc * invs[m];
}

// =================================================================
// launch
// =================================================================
extern "C" void kernel_launch(void* const* d_in, const int* in_sizes, int n_in,
                              void* d_out, int out_size)
{
    const float* X  = (const float*)d_in[0];
    const float* Wq = (const float*)d_in[1];
    const float* bq = (const float*)d_in[2];
    const float* Wk = (const float*)d_in[3];
    const float* bk = (const float*)d_in[4];
    const float* Wv = (const float*)d_in[5];
    const float* bv = (const float*)d_in[6];
    const float* Wo = (const float*)d_in[7];
    const float* bo = (const float*)d_in[8];
    float* out = (float*)d_out;

    float *pq, *pk, *pv, *pc;
    cudaGetSymbolAddress((void**)&pq, g_q);
    cudaGetSymbolAddress((void**)&pk, g_k);
    cudaGetSymbolAddress((void**)&pv, g_v);
    cudaGetSymbolAddress((void**)&pc, g_ctx);

    cudaFuncSetAttribute(frame_attn, cudaFuncAttributeMaxDynamicSharedMemorySize,
                         FRAME_SMEM_BYTES);

    dim3 gg(EW / 128, ROWS / 64);   // (6, 589)

    const float scale = 0.125f;     // 64^-0.5
    sgemm_bias<<<gg, 256>>>(X, Wq, bq, pq, scale);
    sgemm_bias<<<gg, 256>>>(X, Wk, bk, pk, 1.0f);
    sgemm_bias<<<gg, 256>>>(X, Wv, bv, pv, 1.0f);

    frame_attn<<<B_ * HH * NF, 256, FRAME_SMEM_BYTES>>>(pq, pk, pv, pc);
    cls_attn<<<B_ * HH, 256>>>(pq, pk, pv, pc);

    sgemm_bias<<<gg, 256>>>(pc, Wo, bo, out, 1.0f);
}

// round 5
// speedup vs baseline: 2.1140x; 2.1140x over previous
#include <cuda_runtime.h>
#include <cuda_bf16.h>
#include <cstdint>

// ---------------- problem constants (fixed shapes) ----------------
#define B_  16
#define MQ  4          // CLS tokens
#define NF  12         // frames
#define LF  196        // tokens per frame
#define HH  12         // heads
#define DH  64         // head dim
#define EW  768        // embed dim
#define TT  2356       // MQ + NF*LF
#define ROWS (B_*TT)   // 37696
#define KL  200        // MQ + LF (frame attention key length)

#define PADROWS 37760  // 295 * 128
#define KP 1536        // split K (hi|lo concat)

// ---------------- scratch (no cudaMalloc allowed) ----------------
__device__ float g_q[(size_t)ROWS * EW];
__device__ float g_k[(size_t)ROWS * EW];
__device__ float g_v[(size_t)ROWS * EW];
__device__ float g_ctx[(size_t)ROWS * EW];
__device__ __nv_bfloat16 g_a2[(size_t)PADROWS * KP];       // split activations
__device__ __nv_bfloat16 g_w2[4][(size_t)EW * KP];         // split transposed weights

// =================================================================
// PTX helpers (sm_100-baseline only: cp.async, ldmatrix, mma.sync)
// =================================================================
static __device__ __forceinline__ uint32_t smem_u32(const void* p) {
    uint32_t a;
    asm("{ .reg .u64 t; cvta.to.shared.u64 t, %1; cvt.u32.u64 %0, t; }" : "=r"(a) : "l"(p));
    return a;
}

#define CP16(dst, src) \
    asm volatile("cp.async.cg.shared.global [%0], [%1], 16;" :: "r"(dst), "l"(src) : "memory")
#define CP_COMMIT() asm volatile("cp.async.commit_group;" ::: "memory")
#define CP_WAIT1()  asm volatile("cp.async.wait_group 1;" ::: "memory")
#define CP_WAIT0()  asm volatile("cp.async.wait_group 0;" ::: "memory")

#define LDSM4(r0, r1, r2, r3, addr) \
    asm volatile("ldmatrix.sync.aligned.m8n8.x4.shared.b16 {%0,%1,%2,%3}, [%4];" \
        : "=r"(r0), "=r"(r1), "=r"(r2), "=r"(r3) : "r"(addr))

#define MMA16816(d, a, b) \
    asm volatile("mma.sync.aligned.m16n8k16.row.col.f32.bf16.bf16.f32 " \
        "{%0,%1,%2,%3}, {%4,%5,%6,%7}, {%8,%9}, {%0,%1,%2,%3};" \
        : "+f"((d)[0]), "+f"((d)[1]), "+f"((d)[2]), "+f"((d)[3]) \
        : "r"((a)[0]), "r"((a)[1]), "r"((a)[2]), "r"((a)[3]), \
          "r"((b)[0]), "r"((b)[1]))

// =================================================================
// split-bf16 conversion kernels
// =================================================================
__global__ __launch_bounds__(256) void split_rows_k(
    const float* __restrict__ in, __nv_bfloat16* __restrict__ out, int rows)
{
    size_t idx = (size_t)blockIdx.x * 256 + threadIdx.x;   // PADROWS*192 exact
    int m  = (int)(idx / 192);
    int q4 = (int)(idx % 192) * 4;
    float4 v = (m < rows) ? *(const float4*)(in + (size_t)m * EW + q4)
                          : make_float4(0.f, 0.f, 0.f, 0.f);
    __nv_bfloat16 h0 = __float2bfloat16(v.x), h1 = __float2bfloat16(v.y);
    __nv_bfloat16 h2 = __float2bfloat16(v.z), h3 = __float2bfloat16(v.w);
    __nv_bfloat16 l0 = __float2bfloat16(v.x - __bfloat162float(h0));
    __nv_bfloat16 l1 = __float2bfloat16(v.y - __bfloat162float(h1));
    __nv_bfloat16 l2 = __float2bfloat16(v.z - __bfloat162float(h2));
    __nv_bfloat16 l3 = __float2bfloat16(v.w - __bfloat162float(h3));
    __nv_bfloat16* oh = out + (size_t)m * KP + q4;
    __nv_bfloat16* ol = oh + EW;
    *(__nv_bfloat162*)(oh)     = __nv_bfloat162(h0, h1);
    *(__nv_bfloat162*)(oh + 2) = __nv_bfloat162(h2, h3);
    *(__nv_bfloat162*)(ol)     = __nv_bfloat162(l0, l1);
    *(__nv_bfloat162*)(ol + 2) = __nv_bfloat162(l2, l3);
}

__global__ __launch_bounds__(256) void split_w_k(
    const float* __restrict__ W, __nv_bfloat16* __restrict__ out)
{
    int idx = blockIdx.x * 256 + threadIdx.x;   // 768*768 exact
    int n = idx / EW, k = idx % EW;
    float w = W[(size_t)k * EW + n];            // transpose: out[n][k]
    __nv_bfloat16 h = __float2bfloat16(w);
    __nv_bfloat16 l = __float2bfloat16(w - __bfloat162float(h));
    out[(size_t)n * KP + k]      = h;
    out[(size_t)n * KP + EW + k] = l;
}

// =================================================================
// mma.sync bf16 GEMM: C(PADROWS x 768) = A2 @ W2t^T, (acc+bias)*scale
// Block 128x128, 8 warps (4m x 2n), warp 32x64, BK=64, 2-stage cp.async.
// Virtual K=2304: chunks (Ahi,Whi) x12, (Ahi,Wlo) x12, (Alo,Whi) x12.
// =================================================================
#define GBK 64
#define TILE_BYTES 16384                 // 128 rows x 128B
#define GSTAGE_BYTES (2 * TILE_BYTES)    // A + B
#define GEMM_SMEM (2 * GSTAGE_BYTES)     // 65536

__global__ __launch_bounds__(256, 1) void gemm_mma(
    const __nv_bfloat16* __restrict__ A, const __nv_bfloat16* __restrict__ Bw,
    const float* __restrict__ bias, float* __restrict__ C, float scale, int mrows)
{
    extern __shared__ __align__(128) char smem[];
    const uint32_t sbase = smem_u32(smem);
    const int tid = threadIdx.x;
    const int warp = tid >> 5, lane = tid & 31;
    const int m0 = blockIdx.y * 128, n0 = blockIdx.x * 128;

    // ---- global->smem load indexing (4 x 16B segs per thread per tile)
    const __nv_bfloat16* baseA[4];
    const __nv_bfloat16* baseB[4];
    uint32_t stOff[4];
#pragma unroll
    for (int i = 0; i < 4; i++) {
        int seg = tid + i * 256;
        int r = seg >> 3, s = seg & 7;
        baseA[i] = A  + (size_t)(m0 + r) * KP + s * 8;
        baseB[i] = Bw + (size_t)(n0 + r) * KP + s * 8;
        stOff[i] = (uint32_t)(r * 128 + ((s ^ (r & 7)) << 4));   // SW128
    }

    // ---- fragment addressing (per lane)
    const int wm = (warp >> 1) * 32;       // warp m offset in tile
    const int wn = (warp & 1) * 64;        // warp n offset in tile
    uint32_t aRow[2]; int aXor[2];
#pragma unroll
    for (int mt = 0; mt < 2; mt++) {
        int r = wm + mt * 16 + (lane & 15);
        aRow[mt] = (uint32_t)(r * 128);
        aXor[mt] = r & 7;
    }
    const int aKh = lane >> 4;
    uint32_t bRow[4]; int bXor[4];
#pragma unroll
    for (int p = 0; p < 4; p++) {
        int r = wn + p * 16 + (lane & 7) + ((lane >> 4) << 3);
        bRow[p] = (uint32_t)(r * 128);
        bXor[p] = r & 7;
    }
    const int bKh = (lane >> 3) & 1;

    float acc[2][8][4];
#pragma unroll
    for (int mt = 0; mt < 2; mt++)
#pragma unroll
        for (int nt = 0; nt < 8; nt++)
#pragma unroll
            for (int c = 0; c < 4; c++) acc[mt][nt][c] = 0.f;

    // ---- stage loader
    auto load_stage = [&](int t, int buf) {
        int r3 = t / 12, j = t % 12;
        int kA = (r3 == 2 ? EW : 0) + j * GBK;
        int kB = (r3 == 1 ? EW : 0) + j * GBK;
        uint32_t sA = sbase + buf * GSTAGE_BYTES;
        uint32_t sB = sA + TILE_BYTES;
#pragma unroll
        for (int i = 0; i < 4; i++) {
            CP16(sA + stOff[i], baseA[i] + kA);
            CP16(sB + stOff[i], baseB[i] + kB);
        }
        CP_COMMIT();
    };

    load_stage(0, 0);

    for (int t = 0; t < 36; t++) {
        if (t + 1 < 36) { load_stage(t + 1, (t + 1) & 1); CP_WAIT1(); }
        else            { CP_WAIT0(); }
        __syncthreads();

        uint32_t sA = sbase + (t & 1) * GSTAGE_BYTES;
        uint32_t sB = sA + TILE_BYTES;
#pragma unroll
        for (int ks = 0; ks < 4; ks++) {
            uint32_t a[2][4], b[8][2];
#pragma unroll
            for (int mt = 0; mt < 2; mt++) {
                uint32_t addr = sA + aRow[mt] + (uint32_t)((((ks << 1) + aKh) ^ aXor[mt]) << 4);
                LDSM4(a[mt][0], a[mt][1], a[mt][2], a[mt][3], addr);
            }
#pragma unroll
            for (int p = 0; p < 4; p++) {
                uint32_t addr = sB + bRow[p] + (uint32_t)((((ks << 1) + bKh) ^ bXor[p]) << 4);
                uint32_t r0, r1, r2, r3;
                LDSM4(r0, r1, r2, r3, addr);
                b[2 * p][0]     = r0;  b[2 * p][1]     = r1;
                b[2 * p + 1][0] = r2;  b[2 * p + 1][1] = r3;
            }
#pragma unroll
            for (int mt = 0; mt < 2; mt++)
#pragma unroll
                for (int nt = 0; nt < 8; nt++)
                    MMA16816(acc[mt][nt], a[mt], b[nt]);
        }
        __syncthreads();
    }

    // ---- epilogue
#pragma unroll
    for (int mt = 0; mt < 2; mt++) {
        int r0 = m0 + wm + mt * 16 + (lane >> 2);
        int r1 = r0 + 8;
#pragma unroll
        for (int nt = 0; nt < 8; nt++) {
            int col = n0 + wn + nt * 8 + ((lane & 3) << 1);
            float bz0 = bias[col], bz1 = bias[col + 1];
            if (r0 < mrows) {
                float2 o = make_float2((acc[mt][nt][0] + bz0) * scale,
                                       (acc[mt][nt][1] + bz1) * scale);
                *(float2*)(C + (size_t)r0 * EW + col) = o;
            }
            if (r1 < mrows) {
                float2 o = make_float2((acc[mt][nt][2] + bz0) * scale,
                                       (acc[mt][nt][3] + bz1) * scale);
                *(float2*)(C + (size_t)r1 * EW + col) = o;
            }
        }
    }
}

// =================================================================
// Frame attention (unchanged, R2-proven)
// =================================================================
#define FRAME_SMEM_FLOATS (KL*65*2 + 32*DH + 32*KL)
#define FRAME_SMEM_BYTES  (FRAME_SMEM_FLOATS * 4)

__global__ __launch_bounds__(256) void frame_attn(
    const float* __restrict__ q, const float* __restrict__ k,
    const float* __restrict__ v, float* __restrict__ ctx)
{
    extern __shared__ float sm[];
    float* Ks = sm;
    float* Vs = Ks + KL * 65;
    float* qs = Vs + KL * 65;
    float* ps = qs + 32 * DH;

    const int n  = blockIdx.x % NF;
    const int bh = blockIdx.x / NF;
    const int h  = bh % HH;
    const int b  = bh / HH;
    const int tid = threadIdx.x;
    const size_t base = (size_t)b * TT * EW + (size_t)h * DH;
    const int tf0 = MQ + n * LF;

    for (int i = tid; i < KL * (DH / 2); i += 256) {
        int kk = i >> 5;
        int d2 = (i & 31) << 1;
        int t  = (kk < MQ) ? kk : (tf0 + kk - MQ);
        const float2 kv2 = *(const float2*)(k + base + (size_t)t * EW + d2);
        const float2 vv2 = *(const float2*)(v + base + (size_t)t * EW + d2);
        Ks[kk * 65 + d2]     = kv2.x;
        Ks[kk * 65 + d2 + 1] = kv2.y;
        Vs[kk * 65 + d2]     = vv2.x;
        Vs[kk * 65 + d2 + 1] = vv2.y;
    }
    __syncthreads();

    const int w = tid >> 5;
    const int lane = tid & 31;
    float* qw = qs + w * 4 * DH;
    float* pw = ps + w * 4 * KL;

    for (int l0 = w * 4; l0 < LF; l0 += 32) {
        for (int i = lane; i < 4 * DH; i += 32) {
            int r = i >> 6, d = i & 63;
            qw[r * DH + d] = q[base + (size_t)(tf0 + l0 + r) * EW + d];
        }
        __syncwarp();

        float mx0 = -1e30f, mx1 = -1e30f, mx2 = -1e30f, mx3 = -1e30f;
        for (int kk = lane; kk < KL; kk += 32) {
            const float* kr = Ks + kk * 65;
            float a0 = 0.f, a1 = 0.f, a2 = 0.f, a3 = 0.f;
#pragma unroll
            for (int d = 0; d < DH; d++) {
                float kv = kr[d];
                a0 += qw[d] * kv;
                a1 += qw[DH + d] * kv;
                a2 += qw[2 * DH + d] * kv;
                a3 += qw[3 * DH + d] * kv;
            }
            pw[0 * KL + kk] = a0;  mx0 = fmaxf(mx0, a0);
            pw[1 * KL + kk] = a1;  mx1 = fmaxf(mx1, a1);
            pw[2 * KL + kk] = a2;  mx2 = fmaxf(mx2, a2);
            pw[3 * KL + kk] = a3;  mx3 = fmaxf(mx3, a3);
        }
#pragma unroll
        for (int s = 16; s; s >>= 1) {
            mx0 = fmaxf(mx0, __shfl_xor_sync(0xffffffffu, mx0, s));
            mx1 = fmaxf(mx1, __shfl_xor_sync(0xffffffffu, mx1, s));
            mx2 = fmaxf(mx2, __shfl_xor_sync(0xffffffffu, mx2, s));
            mx3 = fmaxf(mx3, __shfl_xor_sync(0xffffffffu, mx3, s));
        }

        float s0 = 0.f, s1 = 0.f, s2 = 0.f, s3 = 0.f;
        for (int kk = lane; kk < KL; kk += 32) {
            float e0 = __expf(pw[0 * KL + kk] - mx0); pw[0 * KL + kk] = e0; s0 += e0;
            float e1 = __expf(pw[1 * KL + kk] - mx1); pw[1 * KL + kk] = e1; s1 += e1;
            float e2 = __expf(pw[2 * KL + kk] - mx2); pw[2 * KL + kk] = e2; s2 += e2;
            float e3 = __expf(pw[3 * KL + kk] - mx3); pw[3 * KL + kk] = e3; s3 += e3;
        }
#pragma unroll
        for (int s = 16; s; s >>= 1) {
            s0 += __shfl_xor_sync(0xffffffffu, s0, s);
            s1 += __shfl_xor_sync(0xffffffffu, s1, s);
            s2 += __shfl_xor_sync(0xffffffffu, s2, s);
            s3 += __shfl_xor_sync(0xffffffffu, s3, s);
        }
        float i0 = 1.f / s0, i1 = 1.f / s1, i2 = 1.f / s2, i3 = 1.f / s3;
        __syncwarp();

        const int d0 = lane << 1;
        float o00 = 0.f, o01 = 0.f, o10 = 0.f, o11 = 0.f;
        float o20 = 0.f, o21 = 0.f, o30 = 0.f, o31 = 0.f;
        for (int kk = 0; kk < KL; kk++) {
            float v0 = Vs[kk * 65 + d0];
            float v1 = Vs[kk * 65 + d0 + 1];
            float p0 = pw[0 * KL + kk];
            float p1 = pw[1 * KL + kk];
            float p2 = pw[2 * KL + kk];
            float p3 = pw[3 * KL + kk];
            o00 += p0 * v0; o01 += p0 * v1;
            o10 += p1 * v0; o11 += p1 * v1;
            o20 += p2 * v0; o21 += p2 * v1;
            o30 += p3 * v0; o31 += p3 * v1;
        }
        {
            size_t o = base + (size_t)(tf0 + l0) * EW + d0;
            ctx[o]          = o00 * i0;  ctx[o + 1]          = o01 * i0;
            ctx[o + EW]     = o10 * i1;  ctx[o + EW + 1]     = o11 * i1;
            ctx[o + 2 * EW] = o20 * i2;  ctx[o + 2 * EW + 1] = o21 * i2;
            ctx[o + 3 * EW] = o30 * i3;  ctx[o + 3 * EW + 1] = o31 * i3;
        }
        __syncwarp();
    }
}

// =================================================================
// CLS attention (unchanged, R2-proven)
// =================================================================
__global__ __launch_bounds__(256) void cls_attn(
    const float* __restrict__ q, const float* __restrict__ k,
    const float* __restrict__ v, float* __restrict__ ctx)
{
    __shared__ float S[4 * TT];
    __shared__ float qs[4 * DH];
    __shared__ float red[256];
    __shared__ float invs[4];

    const int bh = blockIdx.x;
    const int h  = bh % HH;
    const int b  = bh / HH;
    const int tid = threadIdx.x;
    const size_t base = (size_t)b * TT * EW + (size_t)h * DH;

    {
        int m = tid >> 6, d = tid & 63;
        qs[tid] = q[base + (size_t)m * EW + d];
    }
    __syncthreads();

    for (int kk = tid; kk < TT; kk += 256) {
        const float* kr = k + base + (size_t)kk * EW;
        float a0 = 0.f, a1 = 0.f, a2 = 0.f, a3 = 0.f;
#pragma unroll
        for (int d = 0; d < DH; d += 4) {
            float4 kv = *(const float4*)(kr + d);
            a0 += qs[d] * kv.x + qs[d + 1] * kv.y + qs[d + 2] * kv.z + qs[d + 3] * kv.w;
            a1 += qs[DH + d] * kv.x + qs[DH + d + 1] * kv.y + qs[DH + d + 2] * kv.z + qs[DH + d + 3] * kv.w;
            a2 += qs[2 * DH + d] * kv.x + qs[2 * DH + d + 1] * kv.y + qs[2 * DH + d + 2] * kv.z + qs[2 * DH + d + 3] * kv.w;
            a3 += qs[3 * DH + d] * kv.x + qs[3 * DH + d + 1] * kv.y + qs[3 * DH + d + 2] * kv.z + qs[3 * DH + d + 3] * kv.w;
        }
        S[0 * TT + kk] = a0;
        S[1 * TT + kk] = a1;
        S[2 * TT + kk] = a2;
        S[3 * TT + kk] = a3;
    }
    __syncthreads();

    for (int m = 0; m < 4; m++) {
        float lm = -1e30f;
        for (int kk = tid; kk < TT; kk += 256) lm = fmaxf(lm, S[m * TT + kk]);
        red[tid] = lm;
        __syncthreads();
        for (int s = 128; s; s >>= 1) {
            if (tid < s) red[tid] = fmaxf(red[tid], red[tid + s]);
            __syncthreads();
        }
        float mxv = red[0];
        __syncthreads();

        float ls = 0.f;
        for (int kk = tid; kk < TT; kk += 256) {
            float e = __expf(S[m * TT + kk] - mxv);
            S[m * TT + kk] = e;
            ls += e;
        }
        red[tid] = ls;
        __syncthreads();
        for (int s = 128; s; s >>= 1) {
            if (tid < s) red[tid] += red[tid + s];
            __syncthreads();
        }
        if (tid == 0) invs[m] = 1.f / red[0];
        __syncthreads();
    }

    const int m = tid >> 6, d = tid & 63;
    const float* Sm = S + m * TT;
    float acc = 0.f;
#pragma unroll 4
    for (int kk = 0; kk < TT; kk++)
        acc += Sm[kk] * v[base + (size_t)kk * EW + d];
    ctx[base + (size_t)m * EW + d] = acc * invs[m];
}

// =================================================================
// launch
// =================================================================
extern "C" void kernel_launch(void* const* d_in, const int* in_sizes, int n_in,
                              void* d_out, int out_size)
{
    const float* X  = (const float*)d_in[0];
    const float* Wq = (const float*)d_in[1];
    const float* bq = (const float*)d_in[2];
    const float* Wk = (const float*)d_in[3];
    const float* bk = (const float*)d_in[4];
    const float* Wv = (const float*)d_in[5];
    const float* bv = (const float*)d_in[6];
    const float* Wo = (const float*)d_in[7];
    const float* bo = (const float*)d_in[8];
    float* out = (float*)d_out;

    float *pq, *pk, *pv, *pc;
    __nv_bfloat16 *pa2, *pw2;
    cudaGetSymbolAddress((void**)&pq, g_q);
    cudaGetSymbolAddress((void**)&pk, g_k);
    cudaGetSymbolAddress((void**)&pv, g_v);
    cudaGetSymbolAddress((void**)&pc, g_ctx);
    cudaGetSymbolAddress((void**)&pa2, g_a2);
    cudaGetSymbolAddress((void**)&pw2, g_w2);

    cudaFuncSetAttribute(gemm_mma, cudaFuncAttributeMaxDynamicSharedMemorySize,
                         GEMM_SMEM);
    cudaFuncSetAttribute(frame_attn, cudaFuncAttributeMaxDynamicSharedMemorySize,
                         FRAME_SMEM_BYTES);

    const float scale = 0.125f;            // 64^-0.5
    dim3 gemm_grid(EW / 128, PADROWS / 128);   // (6, 295)

    split_rows_k<<<(PADROWS * 192) / 256, 256>>>(X, pa2, ROWS);
    split_w_k<<<(EW * EW) / 256, 256>>>(Wq, pw2 + 0 * (size_t)EW * KP);
    split_w_k<<<(EW * EW) / 256, 256>>>(Wk, pw2 + 1 * (size_t)EW * KP);
    split_w_k<<<(EW * EW) / 256, 256>>>(Wv, pw2 + 2 * (size_t)EW * KP);
    split_w_k<<<(EW * EW) / 256, 256>>>(Wo, pw2 + 3 * (size_t)EW * KP);

    gemm_mma<<<gemm_grid, 256, GEMM_SMEM>>>(pa2, pw2 + 0 * (size_t)EW * KP, bq, pq, scale, ROWS);
    gemm_mma<<<gemm_grid, 256, GEMM_SMEM>>>(pa2, pw2 + 1 * (size_t)EW * KP, bk, pk, 1.0f, ROWS);
    gemm_mma<<<gemm_grid, 256, GEMM_SMEM>>>(pa2, pw2 + 2 * (size_t)EW * KP, bv, pv, 1.0f, ROWS);

    frame_attn<<<B_ * HH * NF, 256, FRAME_SMEM_BYTES>>>(pq, pk, pv, pc);
    cls_attn<<<B_ * HH, 256>>>(pq, pk, pv, pc);

    split_rows_k<<<(PADROWS * 192) / 256, 256>>>(pc, pa2, ROWS);
    gemm_mma<<<gemm_grid, 256, GEMM_SMEM>>>(pa2, pw2 + 3 * (size_t)EW * KP, bo, out, 1.0f, ROWS);
}